// round 16
// baseline (speedup 1.0000x reference)
#include <cuda_runtime.h>
#include <cuda_fp16.h>
#include <cstdint>

// Problem constants (fixed by the dataset)
#define TT 512
#define BB 32
#define NN 64
#define KK 32
#define SAMP_PER_B (TT * NN)                 // 32768 samples per batch element
#define SLICES 32                            // sample-slices per batch
#define SAMP_PER_CTA (SAMP_PER_B / SLICES)   // 1024
#define CHUNK 128
#define NCHUNK (SAMP_PER_CTA / CHUNK)        // 8

// smem tables: 32 rows (modes) x 256B (128 samples x fp16), padded to 272B
// stride (17*16B -> ldmatrix conflict-free). Single buffer (R13-proven).
#define ROW_STRIDE 272
#define TBL_BYTES (32 * ROW_STRIDE)          // 8704
// epilogue reuse: 4 warp regions of 32 rows x 36 floats
#define EPI_WARP_F 1152                      // 4608 B per warp region
#define SMEM_BYTES 18560                     // max(2*8704, 4*4608) + pad

#define NCTA (SLICES * BB)                   // 1024
#define TAIL_BLOCKS 40                       // 32 S-reduce + 8 u-sum

// Deterministic scratch (no device allocation allowed)
__device__ float g_part[NCTA * 1024];        // 4 MB
__device__ float g_berg[BB];
__device__ float g_upart[8];
__device__ int   g_ctr;                      // arrival counter (self-resetting)

__device__ __forceinline__ uint32_t smem_u32(const void* p) {
    uint32_t a;
    asm("{ .reg .u64 t; cvta.to.shared.u64 t, %1; cvt.u32.u64 %0, t; }"
        : "=r"(a) : "l"(p));
    return a;
}

#define LDSM_X4(r0, r1, r2, r3, addr) \
    asm volatile("ldmatrix.sync.aligned.m8n8.x4.shared.b16 {%0,%1,%2,%3}, [%4];" \
                 : "=r"(r0), "=r"(r1), "=r"(r2), "=r"(r3) : "r"(addr))

#define MMA16816F16(d, a, bf) \
    asm volatile("mma.sync.aligned.m16n8k16.row.col.f32.f16.f16.f32 " \
                 "{%0,%1,%2,%3}, {%4,%5,%6,%7}, {%8,%9}, {%0,%1,%2,%3};" \
                 : "+f"((d)[0]), "+f"((d)[1]), "+f"((d)[2]), "+f"((d)[3]) \
                 : "r"((a)[0]), "r"((a)[1]), "r"((a)[2]), "r"((a)[3]), \
                   "r"((bf)[0]), "r"((bf)[1]))

#define STS32(addr, v) \
    asm volatile("st.shared.b32 [%0], %1;" :: "r"(addr), "r"(v) : "memory")

// ============================================================================
// Pass 1: warp-level fp16 tensor-core batched GEMM (R13-proven structure:
// gen -> sync -> mma -> sync, single buffer, 1024 CTAs) with REGISTER
// PREFETCH of the next chunk's x values so the per-chunk L2/DRAM load
// latency is hidden under the current chunk's gen+mma (~2000 cyc of cover).
// ============================================================================
__global__ void __launch_bounds__(128, 6)
pass1_kernel(const float* __restrict__ x, const float* __restrict__ L) {
    __shared__ __align__(16) unsigned char sm[SMEM_BYTES];

    const int tid   = threadIdx.x;
    const int lane  = tid & 31;
    const int w     = tid >> 5;
    const int slice = blockIdx.x;
    const int b     = blockIdx.y;

    const uint32_t base = smem_u32(sm);
    const uint32_t SA = base;                 // dim0 table (A: p modes)
    const uint32_t SB = base + TBL_BYTES;     // dim1 table (B: q modes)

    // --- generator role: thread t -> dim = t>>6, sample-pair sp = t&63 ---
    const int   gdim = tid >> 6;
    const int   sp   = tid & 63;
    const float invL = 3.14159265358979323846f / __ldg(&L[gdim]);
    const uint32_t gBase = (gdim ? SB : SA) + 4u * sp;

    // --- ldmatrix lane addressing (proven mapping) ---
    const int blk = lane >> 3, within = lane & 7;
    const uint32_t aAddr0 = SA + (uint32_t)(((blk & 1) * 8 + within) * ROW_STRIDE
                                            + (blk >> 1) * 16);
    const uint32_t bAddr0 = SB + (uint32_t)(((blk >> 1) * 8 + within) * ROW_STRIDE
                                            + (blk & 1) * 16);

    float acc[2][4][4];
#pragma unroll
    for (int mt = 0; mt < 2; mt++)
#pragma unroll
        for (int nt = 0; nt < 4; nt++)
#pragma unroll
            for (int r = 0; r < 4; r++) acc[mt][nt][r] = 0.0f;

    // x address for chunk c (two samples: n0 and n0+1)
    auto xaddr = [&](int c) {
        const int t_idx = slice * 16 + c * 2 + (sp >> 5);
        const int n0    = (2 * sp) & 63;
        return x + (((size_t)(t_idx * BB + b)) * NN + n0) * 2 + gdim;
    };

    // prefetch chunk 0
    const float* xp0 = xaddr(0);
    float xa = __ldg(xp0), xb = __ldg(xp0 + 2);

    for (int chunk = 0; chunk < NCHUNK; chunk++) {
        // ---- issue next chunk's x loads FIRST (hidden under gen+mma) ----
        float nxa = 0.0f, nxb = 0.0f;
        if (chunk + 1 < NCHUNK) {
            const float* np = xaddr(chunk + 1);
            nxa = __ldg(np);
            nxb = __ldg(np + 2);
        }

        // ---- generate fp16 cos tables for this chunk's 128 samples ----
        {
            const float c1a = __cosf(xa * invL);
            const float c1b = __cosf(xb * invL);
            const float c2a = fmaf(c1a + c1a, c1a, -1.0f);   // cos 2theta
            const float c2b = fmaf(c1b + c1b, c1b, -1.0f);
            const float t2a = c2a + c2a, t2b = c2b + c2b;
            // even chain: modes 0,2,4,... ; odd chain: modes 1,3,5,...
            float ea0 = 1.0f, ea1 = c2a;
            float eb0 = 1.0f, eb1 = c2b;
            float oa0 = c1a,  oa1 = fmaf(t2a, c1a, -c1a);
            float ob0 = c1b,  ob1 = fmaf(t2b, c1b, -c1b);
#pragma unroll
            for (int i = 0; i < 16; i++) {
                uint32_t ep, op;
                asm("cvt.rn.f16x2.f32 %0, %1, %2;" : "=r"(ep) : "f"(eb0), "f"(ea0));
                asm("cvt.rn.f16x2.f32 %0, %1, %2;" : "=r"(op) : "f"(ob0), "f"(oa0));
                STS32(gBase + (uint32_t)((2 * i) * ROW_STRIDE), ep);
                STS32(gBase + (uint32_t)((2 * i + 1) * ROW_STRIDE), op);
                const float na = fmaf(t2a, ea1, -ea0); ea0 = ea1; ea1 = na;
                const float nb = fmaf(t2b, eb1, -eb0); eb0 = eb1; eb1 = nb;
                const float ma = fmaf(t2a, oa1, -oa0); oa0 = oa1; oa1 = ma;
                const float mb = fmaf(t2b, ob1, -ob0); ob0 = ob1; ob1 = mb;
            }
        }
        __syncthreads();

        // ---- consume: 2 ksteps of 16 samples per warp ----
#pragma unroll
        for (int j = 0; j < 2; j++) {
            const uint32_t kb = (uint32_t)(w * 64 + j * 32);
            uint32_t A[2][4], Bf[4][2];
            LDSM_X4(A[0][0], A[0][1], A[0][2], A[0][3], aAddr0 + kb);
            LDSM_X4(A[1][0], A[1][1], A[1][2], A[1][3],
                    aAddr0 + (uint32_t)(16 * ROW_STRIDE) + kb);
            LDSM_X4(Bf[0][0], Bf[0][1], Bf[1][0], Bf[1][1], bAddr0 + kb);
            LDSM_X4(Bf[2][0], Bf[2][1], Bf[3][0], Bf[3][1],
                    bAddr0 + (uint32_t)(16 * ROW_STRIDE) + kb);
#pragma unroll
            for (int mt = 0; mt < 2; mt++)
#pragma unroll
                for (int nt = 0; nt < 4; nt++)
                    MMA16816F16(acc[mt][nt], A[mt], Bf[nt]);
        }

        xa = nxa;
        xb = nxb;
        __syncthreads();
    }

    // ---- epilogue: warp 32x32 tiles -> smem (reuse table region) ----
    {
        float* eb = (float*)sm + w * EPI_WARP_F;
        const int gID = lane >> 2, tg = lane & 3;
#pragma unroll
        for (int mt = 0; mt < 2; mt++) {
            const int r0 = mt * 16 + gID;
#pragma unroll
            for (int nt = 0; nt < 4; nt++) {
                const int c = nt * 8 + 2 * tg;
                *(float2*)(eb + r0 * 36 + c)       = make_float2(acc[mt][nt][0], acc[mt][nt][1]);
                *(float2*)(eb + (r0 + 8) * 36 + c) = make_float2(acc[mt][nt][2], acc[mt][nt][3]);
            }
        }
    }
    __syncthreads();

    // ---- sum 4 warp tiles, write partial S tile (vectorized) ----
    {
        const float* smf = (const float*)sm;
        const int p  = tid >> 2;
        const int q0 = (tid & 3) * 8;
        float4 s0 = make_float4(0.f, 0.f, 0.f, 0.f);
        float4 s1 = s0;
#pragma unroll
        for (int ww = 0; ww < 4; ww++) {
            const float4* r = (const float4*)(smf + ww * EPI_WARP_F + p * 36 + q0);
            const float4 v0 = r[0], v1 = r[1];
            s0.x += v0.x; s0.y += v0.y; s0.z += v0.z; s0.w += v0.w;
            s1.x += v1.x; s1.y += v1.y; s1.z += v1.z; s1.w += v1.w;
        }
        float4* dst = (float4*)(g_part
                                + ((size_t)b * SLICES + slice) * 1024
                                + p * 32 + q0);
        dst[0] = s0;
        dst[1] = s1;
    }
}

// ============================================================================
// Tail kernel (single launch): blocks 0..31 do the per-batch weighted
// squared-error over modes; blocks 32..39 do |u|^2 partial sums. The LAST
// block to arrive (fence + atomic counter) performs the final deterministic
// combine into out. Counter self-resets for graph replay.
// ============================================================================
__global__ void tail_kernel(const float* __restrict__ cd,
                            const float* __restrict__ nf,
                            const float* __restrict__ nw,
                            const float4* __restrict__ u4,
                            float* __restrict__ out) {
    const int tid = threadIdx.x;   // 256
    __shared__ float red[256];

    if (blockIdx.x < BB) {
        const int b = blockIdx.x;
        float4 s = make_float4(0.f, 0.f, 0.f, 0.f);
        const float* basep = g_part + (size_t)b * SLICES * 1024 + tid * 4;
#pragma unroll
        for (int sl = 0; sl < SLICES; sl++) {
            const float4 v = *(const float4*)(basep + sl * 1024);
            s.x += v.x; s.y += v.y; s.z += v.z; s.w += v.w;
        }
        const float4 vnf = *(const float4*)(nf + tid * 4);
        const float4 vcd = *(const float4*)(cd + tid * 4);
        const float4 vnw = *(const float4*)(nw + tid * 4);
        const float inv = 1.0f / (float)SAMP_PER_B;
        const float d0 = s.x * inv / vnf.x - vcd.x;
        const float d1 = s.y * inv / vnf.y - vcd.y;
        const float d2 = s.z * inv / vnf.z - vcd.z;
        const float d3 = s.w * inv / vnf.w - vcd.w;
        red[tid] = d0 * d0 * vnw.x + d1 * d1 * vnw.y
                 + d2 * d2 * vnw.z + d3 * d3 * vnw.w;
        __syncthreads();
        for (int off = 128; off > 0; off >>= 1) {
            if (tid < off) red[tid] += red[tid + off];
            __syncthreads();
        }
        if (tid == 0) g_berg[b] = red[0];
    } else {
        const int ub = blockIdx.x - BB;      // 0..7
        // u: 2,097,152 floats = 524,288 float4; 65,536 float4 per block
        float local = 0.0f;
        const float4* up = u4 + (size_t)ub * 65536 + tid;
#pragma unroll 8
        for (int i = 0; i < 256; i++) {
            const float4 v = up[i * 256];
            local = fmaf(v.x, v.x, local);
            local = fmaf(v.y, v.y, local);
            local = fmaf(v.z, v.z, local);
            local = fmaf(v.w, v.w, local);
        }
        red[tid] = local;
        __syncthreads();
        for (int off = 128; off > 0; off >>= 1) {
            if (tid < off) red[tid] += red[tid + off];
            __syncthreads();
        }
        if (tid == 0) g_upart[ub] = red[0];
    }

    // ---- last-block final combine (deterministic fixed-order sum) ----
    if (tid == 0) {
        __threadfence();
        const int arrived = atomicAdd(&g_ctr, 1);
        if (arrived == TAIL_BLOCKS - 1) {
            __threadfence();
            float se = 0.0f;
#pragma unroll
            for (int i = 0; i < BB; i++) se += g_berg[i];
            float us = 0.0f;
#pragma unroll
            for (int i = 0; i < 8; i++) us += g_upart[i];
            const float UC = 1.0e-3f / (2.0f * (float)SAMP_PER_B * (float)BB);
            out[0] = se + us * UC;
            g_ctr = 0;   // self-reset for next graph replay
        }
    }
}

// ============================================================================
// Launch
// ============================================================================
extern "C" void kernel_launch(void* const* d_in, const int* in_sizes, int n_in,
                              void* d_out, int out_size) {
    const float* x  = (const float*)d_in[0];
    const float* u  = (const float*)d_in[1];
    const float* L  = (const float*)d_in[2];
    const float* cd = (const float*)d_in[3];
    const float* nf = (const float*)d_in[4];
    const float* nw = (const float*)d_in[5];
    float* out = (float*)d_out;

    dim3 grid1(SLICES, BB);               // 32 x 32 = 1024 CTAs
    pass1_kernel<<<grid1, 128>>>(x, L);
    tail_kernel<<<TAIL_BLOCKS, 256>>>(cd, nf, nw, (const float4*)u, out);
}

// round 17
// speedup vs baseline: 1.1391x; 1.1391x over previous
#include <cuda_runtime.h>
#include <cuda_fp16.h>
#include <cstdint>

// Problem constants (fixed by the dataset)
#define TT 512
#define BB 32
#define NN 64
#define KK 32
#define SAMP_PER_B (TT * NN)                 // 32768 samples per batch element
#define SLICES 32                            // sample-slices per batch
#define SAMP_PER_CTA (SAMP_PER_B / SLICES)   // 1024
#define CHUNK 128
#define NCHUNK (SAMP_PER_CTA / CHUNK)        // 8

// smem tables: 32 rows (modes) x 256B (128 samples x fp16), padded to 272B
// stride (17*16B -> ldmatrix conflict-free). Single buffer (R13-proven).
#define ROW_STRIDE 272
#define TBL_BYTES (32 * ROW_STRIDE)          // 8704
// epilogue reuse: 4 warp regions of 32 rows x 36 floats
#define EPI_WARP_F 1152                      // 4608 B per warp region
#define SMEM_BYTES 18560                     // max(2*8704, 4*4608) + pad

#define NCTA (SLICES * BB)                   // 1024
#define U_TAIL_BLOCKS 256                    // 8 MB of u / 32 KB per block
#define TAIL_BLOCKS (BB + U_TAIL_BLOCKS)     // 288

// Deterministic scratch (no device allocation allowed)
__device__ float g_part[NCTA * 1024];        // 4 MB
__device__ float g_berg[BB];
__device__ float g_upart[U_TAIL_BLOCKS];
__device__ int   g_ctr;                      // arrival counter (self-resetting)

__device__ __forceinline__ uint32_t smem_u32(const void* p) {
    uint32_t a;
    asm("{ .reg .u64 t; cvta.to.shared.u64 t, %1; cvt.u32.u64 %0, t; }"
        : "=r"(a) : "l"(p));
    return a;
}

#define LDSM_X4(r0, r1, r2, r3, addr) \
    asm volatile("ldmatrix.sync.aligned.m8n8.x4.shared.b16 {%0,%1,%2,%3}, [%4];" \
                 : "=r"(r0), "=r"(r1), "=r"(r2), "=r"(r3) : "r"(addr))

#define MMA16816F16(d, a, bf) \
    asm volatile("mma.sync.aligned.m16n8k16.row.col.f32.f16.f16.f32 " \
                 "{%0,%1,%2,%3}, {%4,%5,%6,%7}, {%8,%9}, {%0,%1,%2,%3};" \
                 : "+f"((d)[0]), "+f"((d)[1]), "+f"((d)[2]), "+f"((d)[3]) \
                 : "r"((a)[0]), "r"((a)[1]), "r"((a)[2]), "r"((a)[3]), \
                   "r"((bf)[0]), "r"((bf)[1]))

#define STS32(addr, v) \
    asm volatile("st.shared.b32 [%0], %1;" :: "r"(addr), "r"(v) : "memory")

// ============================================================================
// Pass 1: warp-level fp16 tensor-core batched GEMM (R13-proven structure:
// gen -> sync -> mma -> sync, single buffer, 1024 CTAs) with register
// prefetch of the next chunk's x values (LDG latency hidden under gen+mma).
// ============================================================================
__global__ void __launch_bounds__(128, 6)
pass1_kernel(const float* __restrict__ x, const float* __restrict__ L) {
    __shared__ __align__(16) unsigned char sm[SMEM_BYTES];

    const int tid   = threadIdx.x;
    const int lane  = tid & 31;
    const int w     = tid >> 5;
    const int slice = blockIdx.x;
    const int b     = blockIdx.y;

    const uint32_t base = smem_u32(sm);
    const uint32_t SA = base;                 // dim0 table (A: p modes)
    const uint32_t SB = base + TBL_BYTES;     // dim1 table (B: q modes)

    // --- generator role: thread t -> dim = t>>6, sample-pair sp = t&63 ---
    const int   gdim = tid >> 6;
    const int   sp   = tid & 63;
    const float invL = 3.14159265358979323846f / __ldg(&L[gdim]);
    const uint32_t gBase = (gdim ? SB : SA) + 4u * sp;

    // --- ldmatrix lane addressing (proven mapping) ---
    const int blk = lane >> 3, within = lane & 7;
    const uint32_t aAddr0 = SA + (uint32_t)(((blk & 1) * 8 + within) * ROW_STRIDE
                                            + (blk >> 1) * 16);
    const uint32_t bAddr0 = SB + (uint32_t)(((blk >> 1) * 8 + within) * ROW_STRIDE
                                            + (blk & 1) * 16);

    float acc[2][4][4];
#pragma unroll
    for (int mt = 0; mt < 2; mt++)
#pragma unroll
        for (int nt = 0; nt < 4; nt++)
#pragma unroll
            for (int r = 0; r < 4; r++) acc[mt][nt][r] = 0.0f;

    // x address for chunk c (two samples: n0 and n0+1)
    auto xaddr = [&](int c) {
        const int t_idx = slice * 16 + c * 2 + (sp >> 5);
        const int n0    = (2 * sp) & 63;
        return x + (((size_t)(t_idx * BB + b)) * NN + n0) * 2 + gdim;
    };

    // prefetch chunk 0
    const float* xp0 = xaddr(0);
    float xa = __ldg(xp0), xb = __ldg(xp0 + 2);

    for (int chunk = 0; chunk < NCHUNK; chunk++) {
        // ---- issue next chunk's x loads FIRST (hidden under gen+mma) ----
        float nxa = 0.0f, nxb = 0.0f;
        if (chunk + 1 < NCHUNK) {
            const float* np = xaddr(chunk + 1);
            nxa = __ldg(np);
            nxb = __ldg(np + 2);
        }

        // ---- generate fp16 cos tables for this chunk's 128 samples ----
        {
            const float c1a = __cosf(xa * invL);
            const float c1b = __cosf(xb * invL);
            const float c2a = fmaf(c1a + c1a, c1a, -1.0f);   // cos 2theta
            const float c2b = fmaf(c1b + c1b, c1b, -1.0f);
            const float t2a = c2a + c2a, t2b = c2b + c2b;
            // even chain: modes 0,2,4,... ; odd chain: modes 1,3,5,...
            float ea0 = 1.0f, ea1 = c2a;
            float eb0 = 1.0f, eb1 = c2b;
            float oa0 = c1a,  oa1 = fmaf(t2a, c1a, -c1a);
            float ob0 = c1b,  ob1 = fmaf(t2b, c1b, -c1b);
#pragma unroll
            for (int i = 0; i < 16; i++) {
                uint32_t ep, op;
                asm("cvt.rn.f16x2.f32 %0, %1, %2;" : "=r"(ep) : "f"(eb0), "f"(ea0));
                asm("cvt.rn.f16x2.f32 %0, %1, %2;" : "=r"(op) : "f"(ob0), "f"(oa0));
                STS32(gBase + (uint32_t)((2 * i) * ROW_STRIDE), ep);
                STS32(gBase + (uint32_t)((2 * i + 1) * ROW_STRIDE), op);
                const float na = fmaf(t2a, ea1, -ea0); ea0 = ea1; ea1 = na;
                const float nb = fmaf(t2b, eb1, -eb0); eb0 = eb1; eb1 = nb;
                const float ma = fmaf(t2a, oa1, -oa0); oa0 = oa1; oa1 = ma;
                const float mb = fmaf(t2b, ob1, -ob0); ob0 = ob1; ob1 = mb;
            }
        }
        __syncthreads();

        // ---- consume: 2 ksteps of 16 samples per warp ----
#pragma unroll
        for (int j = 0; j < 2; j++) {
            const uint32_t kb = (uint32_t)(w * 64 + j * 32);
            uint32_t A[2][4], Bf[4][2];
            LDSM_X4(A[0][0], A[0][1], A[0][2], A[0][3], aAddr0 + kb);
            LDSM_X4(A[1][0], A[1][1], A[1][2], A[1][3],
                    aAddr0 + (uint32_t)(16 * ROW_STRIDE) + kb);
            LDSM_X4(Bf[0][0], Bf[0][1], Bf[1][0], Bf[1][1], bAddr0 + kb);
            LDSM_X4(Bf[2][0], Bf[2][1], Bf[3][0], Bf[3][1],
                    bAddr0 + (uint32_t)(16 * ROW_STRIDE) + kb);
#pragma unroll
            for (int mt = 0; mt < 2; mt++)
#pragma unroll
                for (int nt = 0; nt < 4; nt++)
                    MMA16816F16(acc[mt][nt], A[mt], Bf[nt]);
        }

        xa = nxa;
        xb = nxb;
        __syncthreads();
    }

    // ---- epilogue: warp 32x32 tiles -> smem (reuse table region) ----
    {
        float* eb = (float*)sm + w * EPI_WARP_F;
        const int gID = lane >> 2, tg = lane & 3;
#pragma unroll
        for (int mt = 0; mt < 2; mt++) {
            const int r0 = mt * 16 + gID;
#pragma unroll
            for (int nt = 0; nt < 4; nt++) {
                const int c = nt * 8 + 2 * tg;
                *(float2*)(eb + r0 * 36 + c)       = make_float2(acc[mt][nt][0], acc[mt][nt][1]);
                *(float2*)(eb + (r0 + 8) * 36 + c) = make_float2(acc[mt][nt][2], acc[mt][nt][3]);
            }
        }
    }
    __syncthreads();

    // ---- sum 4 warp tiles, write partial S tile (vectorized) ----
    {
        const float* smf = (const float*)sm;
        const int p  = tid >> 2;
        const int q0 = (tid & 3) * 8;
        float4 s0 = make_float4(0.f, 0.f, 0.f, 0.f);
        float4 s1 = s0;
#pragma unroll
        for (int ww = 0; ww < 4; ww++) {
            const float4* r = (const float4*)(smf + ww * EPI_WARP_F + p * 36 + q0);
            const float4 v0 = r[0], v1 = r[1];
            s0.x += v0.x; s0.y += v0.y; s0.z += v0.z; s0.w += v0.w;
            s1.x += v1.x; s1.y += v1.y; s1.z += v1.z; s1.w += v1.w;
        }
        float4* dst = (float4*)(g_part
                                + ((size_t)b * SLICES + slice) * 1024
                                + p * 32 + q0);
        dst[0] = s0;
        dst[1] = s1;
    }
}

// ============================================================================
// Tail kernel (single launch, 288 blocks): blocks 0..31 -> per-batch weighted
// squared-error over modes; blocks 32..287 -> |u|^2 partials (32 KB each,
// full-chip DRAM parallelism). Last block to arrive (fence + atomic counter)
// performs the final deterministic fixed-order combine. Counter self-resets.
// ============================================================================
__global__ void tail_kernel(const float* __restrict__ cd,
                            const float* __restrict__ nf,
                            const float* __restrict__ nw,
                            const float4* __restrict__ u4,
                            float* __restrict__ out) {
    const int tid = threadIdx.x;   // 256
    __shared__ float red[256];

    if (blockIdx.x < BB) {
        const int b = blockIdx.x;
        float4 s = make_float4(0.f, 0.f, 0.f, 0.f);
        const float* basep = g_part + (size_t)b * SLICES * 1024 + tid * 4;
#pragma unroll
        for (int sl = 0; sl < SLICES; sl++) {
            const float4 v = *(const float4*)(basep + sl * 1024);
            s.x += v.x; s.y += v.y; s.z += v.z; s.w += v.w;
        }
        const float4 vnf = *(const float4*)(nf + tid * 4);
        const float4 vcd = *(const float4*)(cd + tid * 4);
        const float4 vnw = *(const float4*)(nw + tid * 4);
        const float inv = 1.0f / (float)SAMP_PER_B;
        const float d0 = s.x * inv / vnf.x - vcd.x;
        const float d1 = s.y * inv / vnf.y - vcd.y;
        const float d2 = s.z * inv / vnf.z - vcd.z;
        const float d3 = s.w * inv / vnf.w - vcd.w;
        red[tid] = d0 * d0 * vnw.x + d1 * d1 * vnw.y
                 + d2 * d2 * vnw.z + d3 * d3 * vnw.w;
        __syncthreads();
        for (int off = 128; off > 0; off >>= 1) {
            if (tid < off) red[tid] += red[tid + off];
            __syncthreads();
        }
        if (tid == 0) g_berg[b] = red[0];
    } else {
        const int ub = blockIdx.x - BB;      // 0..255
        // u: 524,288 float4 total; 2048 float4 (32 KB) per block
        float local = 0.0f;
        const float4* up = u4 + (size_t)ub * 2048 + tid;
#pragma unroll
        for (int i = 0; i < 8; i++) {
            const float4 v = up[i * 256];
            local = fmaf(v.x, v.x, local);
            local = fmaf(v.y, v.y, local);
            local = fmaf(v.z, v.z, local);
            local = fmaf(v.w, v.w, local);
        }
        red[tid] = local;
        __syncthreads();
        for (int off = 128; off > 0; off >>= 1) {
            if (tid < off) red[tid] += red[tid + off];
            __syncthreads();
        }
        if (tid == 0) g_upart[ub] = red[0];
    }

    // ---- last-block final combine (deterministic fixed-order sum) ----
    if (tid == 0) {
        __threadfence();
        const int arrived = atomicAdd(&g_ctr, 1);
        if (arrived == TAIL_BLOCKS - 1) {
            __threadfence();
            float se = 0.0f;
#pragma unroll
            for (int i = 0; i < BB; i++) se += g_berg[i];
            float us = 0.0f;
#pragma unroll 8
            for (int i = 0; i < U_TAIL_BLOCKS; i++) us += g_upart[i];
            const float UC = 1.0e-3f / (2.0f * (float)SAMP_PER_B * (float)BB);
            out[0] = se + us * UC;
            g_ctr = 0;   // self-reset for next graph replay
        }
    }
}

// ============================================================================
// Launch
// ============================================================================
extern "C" void kernel_launch(void* const* d_in, const int* in_sizes, int n_in,
                              void* d_out, int out_size) {
    const float* x  = (const float*)d_in[0];
    const float* u  = (const float*)d_in[1];
    const float* L  = (const float*)d_in[2];
    const float* cd = (const float*)d_in[3];
    const float* nf = (const float*)d_in[4];
    const float* nw = (const float*)d_in[5];
    float* out = (float*)d_out;

    dim3 grid1(SLICES, BB);               // 32 x 32 = 1024 CTAs
    pass1_kernel<<<grid1, 128>>>(x, L);
    tail_kernel<<<TAIL_BLOCKS, 256>>>(cd, nf, nw, (const float4*)u, out);
}